// round 10
// baseline (speedup 1.0000x reference)
#include <cuda_runtime.h>
#include <cuda_bf16.h>
#include <mma.h>
#include <math.h>
#include <stdint.h>

using namespace nvcuda;

// Problem constants
#define N_ROWS   1024
#define IN_F     2048
#define BOOKS    8
#define OUT_F    4096
#define LW       256
#define WORDS    256
#define SC       30.0f
#define MARGIN   0.5f
#define EPS      1e-12f

#define OUT1_ELEMS ((size_t)N_ROWS * BOOKS * OUT_F)
#define OFF2       OUT1_ELEMS
#define OFF3       (2 * OUT1_ELEMS)

// bf16 hi/lo split operands (emulated fp32 via 3 bf16 MMAs)
__device__ __nv_bfloat16 g_xh[BOOKS * N_ROWS * LW];
__device__ __nv_bfloat16 g_xl[BOOKS * N_ROWS * LW];
__device__ __nv_bfloat16 g_sh[BOOKS * N_ROWS * LW];
__device__ __nv_bfloat16 g_sl[BOOKS * N_ROWS * LW];
__device__ __nv_bfloat16 g_wh[BOOKS * OUT_F * LW];
__device__ __nv_bfloat16 g_wl[BOOKS * OUT_F * LW];
__device__ __nv_bfloat16 g_mh[BOOKS * LW * WORDS];
__device__ __nv_bfloat16 g_ml[BOOKS * LW * WORDS];
__device__ __nv_bfloat16 g_cbTh[BOOKS * WORDS * LW];
__device__ __nv_bfloat16 g_cbTl[BOOKS * WORDS * LW];

__device__ __forceinline__ uint32_t smem_u32(const void* p) {
    uint32_t a;
    asm("{ .reg .u64 t; cvta.to.shared.u64 t, %1; cvt.u32.u64 %0, t; }"
        : "=r"(a) : "l"(p));
    return a;
}

#define CP_ASYNC16(dst, src) \
    asm volatile("cp.async.cg.shared.global [%0], [%1], 16;" \
        :: "r"(dst), "l"(src) : "memory")
#define CP_COMMIT() asm volatile("cp.async.commit_group;" ::: "memory")
#define CP_WAIT(n)  asm volatile("cp.async.wait_group %0;" :: "n"(n) : "memory")

__device__ __forceinline__ void split_bf16(float v, __nv_bfloat16& h, __nv_bfloat16& l) {
    h = __float2bfloat16(v);
    l = __float2bfloat16(v - __bfloat162float(h));
}

// ---------------------------------------------------------------------------
// Kernel 1: row-normalize weight -> bf16 hi/lo. One warp per 256-elem row.
// ---------------------------------------------------------------------------
__global__ void __launch_bounds__(256) k_norm_w(const float* __restrict__ w) {
    int row  = blockIdx.x * 8 + (threadIdx.x >> 5);
    int lane = threadIdx.x & 31;
    const float* src = w + (size_t)row * LW + lane * 8;
    float4 a = *(const float4*)src;
    float4 c = *(const float4*)(src + 4);
    float ss = a.x*a.x + a.y*a.y + a.z*a.z + a.w*a.w
             + c.x*c.x + c.y*c.y + c.z*c.z + c.w*c.w;
    #pragma unroll
    for (int off = 16; off; off >>= 1) ss += __shfl_xor_sync(0xffffffffu, ss, off);
    float inv = 1.0f / fmaxf(sqrtf(ss), EPS);
    __align__(16) __nv_bfloat16 h8[8], l8[8];
    float v[8] = {a.x, a.y, a.z, a.w, c.x, c.y, c.z, c.w};
    #pragma unroll
    for (int j = 0; j < 8; j++) split_bf16(v[j] * inv, h8[j], l8[j]);
    *(uint4*)(g_wh + (size_t)row * LW + lane * 8) = *(uint4*)h8;
    *(uint4*)(g_wl + (size_t)row * LW + lane * 8) = *(uint4*)l8;
}

// ---------------------------------------------------------------------------
// Kernel 2a: elementwise split of mlp -> g_mh/g_ml
// ---------------------------------------------------------------------------
__global__ void __launch_bounds__(256) k_split_mlp(const float* __restrict__ m) {
    size_t i = ((size_t)blockIdx.x * 256 + threadIdx.x) * 4;
    float4 v = *(const float4*)(m + i);
    __align__(8) __nv_bfloat16 h4[4], l4[4];
    split_bf16(v.x, h4[0], l4[0]); split_bf16(v.y, h4[1], l4[1]);
    split_bf16(v.z, h4[2], l4[2]); split_bf16(v.w, h4[3], l4[3]);
    *(uint2*)(g_mh + i) = *(uint2*)h4;
    *(uint2*)(g_ml + i) = *(uint2*)l4;
}

// ---------------------------------------------------------------------------
// Kernel 2b: transpose codebooks + split: cbT[b][w][d] = cb[b][d][w]
// ---------------------------------------------------------------------------
__global__ void k_transpose_cb(const float* __restrict__ cb) {
    __shared__ float t[32][33];
    int b  = blockIdx.z;
    int d0 = blockIdx.x * 32;
    int w0 = blockIdx.y * 32;
    const float* src = cb + (size_t)b * LW * WORDS;
    for (int i = threadIdx.y; i < 32; i += 8)
        t[i][threadIdx.x] = src[(size_t)(d0 + i) * WORDS + w0 + threadIdx.x];
    __syncthreads();
    for (int i = threadIdx.y; i < 32; i += 8) {
        float v = t[threadIdx.x][i];
        __nv_bfloat16 h, l;
        split_bf16(v, h, l);
        size_t o = (size_t)b * WORDS * LW + (size_t)(w0 + i) * LW + d0 + threadIdx.x;
        g_cbTh[o] = h;
        g_cbTl[o] = l;
    }
}

// ---------------------------------------------------------------------------
// Kernel 3: WMMA bf16x3 features. One CTA per (book, 64 rows). 256 threads.
// ---------------------------------------------------------------------------
#define FLDA 264                 // bf16 smem pitch
#define FLDL 260                 // fp32 smem pitch
#define F_XA_H 0
#define F_XA_L 33792
#define F_BB_H 67584
#define F_BB_L 101376
#define F_LL   135168
#define F_DYN  (F_LL + 64 * FLDL * 4)   // 201728

__global__ void __launch_bounds__(256) k_feat(const float* __restrict__ input,
                                              float* __restrict__ out) {
    extern __shared__ __align__(16) char fsm[];
    __nv_bfloat16* XH = (__nv_bfloat16*)(fsm + F_XA_H);
    __nv_bfloat16* XL = (__nv_bfloat16*)(fsm + F_XA_L);
    __nv_bfloat16* BH = (__nv_bfloat16*)(fsm + F_BB_H);
    __nv_bfloat16* BL = (__nv_bfloat16*)(fsm + F_BB_L);
    float*         LL = (float*)(fsm + F_LL);
    __shared__ float part[64][4];
    __shared__ float rinv[64];

    int tid = threadIdx.x, wid = tid >> 5, lane = tid & 31;
    int n0 = blockIdx.x * 64;
    int b  = blockIdx.y;

    // ---- phase 1: load x, split into XA, per-row sumsq
    {
        int r = tid >> 2, q = tid & 3;
        const float* srcp = input + (size_t)(n0 + r) * IN_F + b * LW + q * 64;
        float ss = 0.0f;
        #pragma unroll
        for (int j = 0; j < 16; j++) {
            float4 v = *(const float4*)(srcp + j * 4);
            __align__(8) __nv_bfloat16 h4[4], l4[4];
            split_bf16(v.x, h4[0], l4[0]); split_bf16(v.y, h4[1], l4[1]);
            split_bf16(v.z, h4[2], l4[2]); split_bf16(v.w, h4[3], l4[3]);
            int c = q * 64 + j * 4;
            *(uint2*)&XH[r * FLDA + c] = *(uint2*)h4;
            *(uint2*)&XL[r * FLDA + c] = *(uint2*)l4;
            ss += v.x*v.x + v.y*v.y + v.z*v.z + v.w*v.w;
        }
        part[r][q] = ss;
    }
    __syncthreads();
    if (tid < 64)
        rinv[tid] = 1.0f / fmaxf(sqrtf(part[tid][0] + part[tid][1] +
                                       part[tid][2] + part[tid][3]), EPS);
    __syncthreads();

    // ---- phase 2: write normalized-x splits to global
    {
        int r = tid >> 2, q = tid & 3;
        float iv = rinv[r];
        const float* srcp = input + (size_t)(n0 + r) * IN_F + b * LW + q * 64;
        size_t go = ((size_t)b * N_ROWS + n0 + r) * LW + q * 64;
        #pragma unroll
        for (int j = 0; j < 16; j++) {
            float4 v = *(const float4*)(srcp + j * 4);
            __align__(8) __nv_bfloat16 h4[4], l4[4];
            split_bf16(v.x * iv, h4[0], l4[0]); split_bf16(v.y * iv, h4[1], l4[1]);
            split_bf16(v.z * iv, h4[2], l4[2]); split_bf16(v.w * iv, h4[3], l4[3]);
            *(uint2*)(g_xh + go + j * 4) = *(uint2*)h4;
            *(uint2*)(g_xl + go + j * 4) = *(uint2*)l4;
        }
    }

    int wm = wid >> 2;
    int wn = wid & 3;
    wmma::fragment<wmma::accumulator, 16, 16, 16, float> acc[2][4];

    // ================= GEMM 1: logits = x @ mlp =================
    #pragma unroll
    for (int im = 0; im < 2; im++)
        #pragma unroll
        for (int jn = 0; jn < 4; jn++) wmma::fill_fragment(acc[im][jn], 0.0f);

    for (int kc = 0; kc < 4; kc++) {
        __syncthreads();
        const __nv_bfloat16* gbh = g_mh + (size_t)b * LW * WORDS + (size_t)kc * 64 * WORDS;
        const __nv_bfloat16* gbl = g_ml + (size_t)b * LW * WORDS + (size_t)kc * 64 * WORDS;
        #pragma unroll
        for (int j = 0; j < 8; j++) {
            int u = j * 256 + tid, row = u >> 5, seg = u & 31;
            *(uint4*)&BH[row * FLDA + seg * 8] = *(const uint4*)(gbh + row * 256 + seg * 8);
            *(uint4*)&BL[row * FLDA + seg * 8] = *(const uint4*)(gbl + row * 256 + seg * 8);
        }
        __syncthreads();
        #pragma unroll
        for (int k = 0; k < 4; k++) {
            wmma::fragment<wmma::matrix_a, 16, 16, 16, __nv_bfloat16, wmma::row_major> ah[2], al[2];
            #pragma unroll
            for (int im = 0; im < 2; im++) {
                int r0 = wm * 32 + im * 16;
                wmma::load_matrix_sync(ah[im], XH + r0 * FLDA + kc * 64 + k * 16, FLDA);
                wmma::load_matrix_sync(al[im], XL + r0 * FLDA + kc * 64 + k * 16, FLDA);
            }
            #pragma unroll
            for (int jn = 0; jn < 4; jn++) {
                int c0 = wn * 64 + jn * 16;
                wmma::fragment<wmma::matrix_b, 16, 16, 16, __nv_bfloat16, wmma::row_major> bh, bl;
                wmma::load_matrix_sync(bh, BH + (k * 16) * FLDA + c0, FLDA);
                wmma::load_matrix_sync(bl, BL + (k * 16) * FLDA + c0, FLDA);
                #pragma unroll
                for (int im = 0; im < 2; im++) {
                    wmma::mma_sync(acc[im][jn], ah[im], bh, acc[im][jn]);
                    wmma::mma_sync(acc[im][jn], ah[im], bl, acc[im][jn]);
                    wmma::mma_sync(acc[im][jn], al[im], bh, acc[im][jn]);
                }
            }
        }
    }
    __syncthreads();
    #pragma unroll
    for (int im = 0; im < 2; im++)
        #pragma unroll
        for (int jn = 0; jn < 4; jn++)
            wmma::store_matrix_sync(LL + (wm * 32 + im * 16) * FLDL + wn * 64 + jn * 16,
                                    acc[im][jn], FLDL, wmma::mem_row_major);
    __syncthreads();

    // ---- softmax per row
    #pragma unroll
    for (int rr = 0; rr < 8; rr++) {
        int r = wid * 8 + rr;
        float4 va = *(float4*)&LL[r * FLDL + lane * 8];
        float4 vb = *(float4*)&LL[r * FLDL + lane * 8 + 4];
        float v[8] = {va.x, va.y, va.z, va.w, vb.x, vb.y, vb.z, vb.w};
        float mx = v[0];
        #pragma unroll
        for (int j = 1; j < 8; j++) mx = fmaxf(mx, v[j]);
        #pragma unroll
        for (int off = 16; off; off >>= 1) mx = fmaxf(mx, __shfl_xor_sync(0xffffffffu, mx, off));
        float sm = 0.0f;
        #pragma unroll
        for (int j = 0; j < 8; j++) { v[j] = expf(v[j] - mx); sm += v[j]; }
        #pragma unroll
        for (int off = 16; off; off >>= 1) sm += __shfl_xor_sync(0xffffffffu, sm, off);
        float inv = 1.0f / sm;
        __align__(16) __nv_bfloat16 h8[8], l8[8];
        #pragma unroll
        for (int j = 0; j < 8; j++) { v[j] *= inv; split_bf16(v[j], h8[j], l8[j]); }
        float* po = out + OFF3 + (size_t)(n0 + r) * (BOOKS * WORDS) + b * WORDS + lane * 8;
        *(float4*)po       = make_float4(v[0], v[1], v[2], v[3]);
        *(float4*)(po + 4) = make_float4(v[4], v[5], v[6], v[7]);
        *(uint4*)&XH[r * FLDA + lane * 8] = *(uint4*)h8;
        *(uint4*)&XL[r * FLDA + lane * 8] = *(uint4*)l8;
    }
    __syncthreads();

    // ================= GEMM 2: s = xc @ cbT =================
    #pragma unroll
    for (int im = 0; im < 2; im++)
        #pragma unroll
        for (int jn = 0; jn < 4; jn++) wmma::fill_fragment(acc[im][jn], 0.0f);

    for (int kc = 0; kc < 4; kc++) {
        __syncthreads();
        const __nv_bfloat16* gbh = g_cbTh + (size_t)b * WORDS * LW + (size_t)kc * 64 * LW;
        const __nv_bfloat16* gbl = g_cbTl + (size_t)b * WORDS * LW + (size_t)kc * 64 * LW;
        #pragma unroll
        for (int j = 0; j < 8; j++) {
            int u = j * 256 + tid, row = u >> 5, seg = u & 31;
            *(uint4*)&BH[row * FLDA + seg * 8] = *(const uint4*)(gbh + row * 256 + seg * 8);
            *(uint4*)&BL[row * FLDA + seg * 8] = *(const uint4*)(gbl + row * 256 + seg * 8);
        }
        __syncthreads();
        #pragma unroll
        for (int k = 0; k < 4; k++) {
            wmma::fragment<wmma::matrix_a, 16, 16, 16, __nv_bfloat16, wmma::row_major> ah[2], al[2];
            #pragma unroll
            for (int im = 0; im < 2; im++) {
                int r0 = wm * 32 + im * 16;
                wmma::load_matrix_sync(ah[im], XH + r0 * FLDA + kc * 64 + k * 16, FLDA);
                wmma::load_matrix_sync(al[im], XL + r0 * FLDA + kc * 64 + k * 16, FLDA);
            }
            #pragma unroll
            for (int jn = 0; jn < 4; jn++) {
                int c0 = wn * 64 + jn * 16;
                wmma::fragment<wmma::matrix_b, 16, 16, 16, __nv_bfloat16, wmma::row_major> bh, bl;
                wmma::load_matrix_sync(bh, BH + (k * 16) * FLDA + c0, FLDA);
                wmma::load_matrix_sync(bl, BL + (k * 16) * FLDA + c0, FLDA);
                #pragma unroll
                for (int im = 0; im < 2; im++) {
                    wmma::mma_sync(acc[im][jn], ah[im], bh, acc[im][jn]);
                    wmma::mma_sync(acc[im][jn], ah[im], bl, acc[im][jn]);
                    wmma::mma_sync(acc[im][jn], al[im], bh, acc[im][jn]);
                }
            }
        }
    }
    __syncthreads();
    #pragma unroll
    for (int im = 0; im < 2; im++)
        #pragma unroll
        for (int jn = 0; jn < 4; jn++)
            wmma::store_matrix_sync(LL + (wm * 32 + im * 16) * FLDL + wn * 64 + jn * 16,
                                    acc[im][jn], FLDL, wmma::mem_row_major);
    __syncthreads();

    // ---- s row norms -> g_sh/g_sl
    #pragma unroll
    for (int rr = 0; rr < 8; rr++) {
        int r = wid * 8 + rr;
        float4 va = *(float4*)&LL[r * FLDL + lane * 8];
        float4 vb = *(float4*)&LL[r * FLDL + lane * 8 + 4];
        float v[8] = {va.x, va.y, va.z, va.w, vb.x, vb.y, vb.z, vb.w};
        float ss = 0.0f;
        #pragma unroll
        for (int j = 0; j < 8; j++) ss += v[j] * v[j];
        #pragma unroll
        for (int off = 16; off; off >>= 1) ss += __shfl_xor_sync(0xffffffffu, ss, off);
        float inv = 1.0f / fmaxf(sqrtf(ss), EPS);
        __align__(16) __nv_bfloat16 h8[8], l8[8];
        #pragma unroll
        for (int j = 0; j < 8; j++) split_bf16(v[j] * inv, h8[j], l8[j]);
        size_t go = ((size_t)b * N_ROWS + n0 + r) * LW + lane * 8;
        *(uint4*)(g_sh + go) = *(uint4*)h8;
        *(uint4*)(g_sl + go) = *(uint4*)l8;
    }
}

// ---------------------------------------------------------------------------
// Kernel 4: WMMA bf16x3 dual GEMM, 512 threads / 16 warps.
// Warps 0-7: acc1 (xn x W). Warps 8-15: acc2 (sn x W). Shared W tiles.
// Per group: 4m x 2n warp grid, warp tile 32x64.
// ---------------------------------------------------------------------------
#define LDT      72
#define TILE_E   (128 * LDT)
#define TILE_B   (TILE_E * 2)
#define STAGE_E  (6 * TILE_E)
#define STAGE_B  (6 * TILE_B)
#define DYN_SMEM (2 * STAGE_B)
#define DPITCH   136
#define REG2     (128 * DPITCH)

__global__ void __launch_bounds__(512, 1) k_gemm_wm(const int* __restrict__ label,
                                                    float* __restrict__ out) {
    extern __shared__ __align__(16) char dsm[];
    __nv_bfloat16* smt = (__nv_bfloat16*)dsm;
    __shared__ int s_lbl[128];

    int tid = threadIdx.x;
    int wid = tid >> 5, lane = tid & 31;
    int nt = blockIdx.x, mt = blockIdx.y, b = blockIdx.z;
    uint32_t smbase = smem_u32(dsm);

    if (tid < 128) s_lbl[tid] = label[mt * 128 + tid];

    const char* pXH = (const char*)(g_xh + ((size_t)b * N_ROWS + mt * 128) * LW);
    const char* pXL = (const char*)(g_xl + ((size_t)b * N_ROWS + mt * 128) * LW);
    const char* pSH = (const char*)(g_sh + ((size_t)b * N_ROWS + mt * 128) * LW);
    const char* pSL = (const char*)(g_sl + ((size_t)b * N_ROWS + mt * 128) * LW);
    const char* pWH = (const char*)(g_wh + ((size_t)b * OUT_F  + nt * 128) * LW);
    const char* pWL = (const char*)(g_wl + ((size_t)b * OUT_F  + nt * 128) * LW);

    // 512 threads: each tile = 1024 16B segments -> 2 per thread.
#define LD1TILE(ptr, t, c_, st_) { \
    _Pragma("unroll") for (int j = 0; j < 2; j++) { \
        int u = j * 512 + tid; int row = u >> 3, seg = u & 7; \
        uint32_t dst = smbase + (st_) * STAGE_B + (t) * TILE_B + row * 144 + seg * 16; \
        const char* src = (ptr) + (size_t)row * 512 + (c_) * 128 + seg * 16; \
        CP_ASYNC16(dst, src); } }
#define LOAD_CHUNK(c_, st_) { \
    LD1TILE(pXH, 0, c_, st_); LD1TILE(pXL, 1, c_, st_); \
    LD1TILE(pSH, 2, c_, st_); LD1TILE(pSL, 3, c_, st_); \
    LD1TILE(pWH, 4, c_, st_); LD1TILE(pWL, 5, c_, st_); \
    CP_COMMIT(); }

    int group = wid >> 3;      // 0: out1 (x), 1: out2 (s)
    int w8 = wid & 7;
    int wm = w8 & 3;           // 32-row block
    int wn = w8 >> 2;          // 64-col block

    wmma::fragment<wmma::accumulator, 16, 16, 16, float> acc[2][4];
    #pragma unroll
    for (int im = 0; im < 2; im++)
        #pragma unroll
        for (int jn = 0; jn < 4; jn++) wmma::fill_fragment(acc[im][jn], 0.0f);

    LOAD_CHUNK(0, 0);
    LOAD_CHUNK(1, 1);

    #pragma unroll
    for (int c = 0; c < 4; c++) {
        if (c < 3) { CP_WAIT(1); } else { CP_WAIT(0); }
        __syncthreads();
        {
            int st = c & 1;
            const __nv_bfloat16* base = smt + st * STAGE_E;
            // group 0 reads x tiles (0,1); group 1 reads s tiles (2,3); both read W (4,5)
            const __nv_bfloat16* tAH = base + (group ? 2 : 0) * TILE_E;
            const __nv_bfloat16* tAL = base + (group ? 3 : 1) * TILE_E;
            const __nv_bfloat16* tWH = base + 4 * TILE_E;
            const __nv_bfloat16* tWL = base + 5 * TILE_E;
            #pragma unroll
            for (int k = 0; k < 4; k++) {
                wmma::fragment<wmma::matrix_a, 16, 16, 16, __nv_bfloat16, wmma::row_major> ah[2], al[2];
                #pragma unroll
                for (int im = 0; im < 2; im++) {
                    int r0 = wm * 32 + im * 16;
                    wmma::load_matrix_sync(ah[im], tAH + r0 * LDT + k * 16, LDT);
                    wmma::load_matrix_sync(al[im], tAL + r0 * LDT + k * 16, LDT);
                }
                #pragma unroll
                for (int jn = 0; jn < 4; jn++) {
                    int c0 = wn * 64 + jn * 16;
                    wmma::fragment<wmma::matrix_b, 16, 16, 16, __nv_bfloat16, wmma::col_major> bwh, bwl;
                    wmma::load_matrix_sync(bwh, tWH + c0 * LDT + k * 16, LDT);
                    wmma::load_matrix_sync(bwl, tWL + c0 * LDT + k * 16, LDT);
                    #pragma unroll
                    for (int im = 0; im < 2; im++) {
                        wmma::mma_sync(acc[im][jn], ah[im], bwh, acc[im][jn]);
                        wmma::mma_sync(acc[im][jn], ah[im], bwl, acc[im][jn]);
                        wmma::mma_sync(acc[im][jn], al[im], bwh, acc[im][jn]);
                    }
                }
            }
        }
        __syncthreads();
        if (c + 2 < 4) { LOAD_CHUNK(c + 2, c & 1); }
    }

    // Stage accumulators to smem (group 0 -> region 1, group 1 -> region 2)
    float* D = (float*)dsm;
    #pragma unroll
    for (int im = 0; im < 2; im++)
        #pragma unroll
        for (int jn = 0; jn < 4; jn++) {
            int r0 = wm * 32 + im * 16;
            int c0 = wn * 64 + jn * 16;
            wmma::store_matrix_sync(D + (size_t)group * REG2 + (size_t)r0 * DPITCH + c0,
                                    acc[im][jn], DPITCH, wmma::mem_row_major);
        }
    __syncthreads();

    {
        int colq = lane;
        for (int r0 = wid; r0 < 128; r0 += 16) {
            int lv = s_lbl[r0];
            int o0 = nt * 128 + colq * 4;
            size_t basep = (size_t)(mt * 128 + r0) * (BOOKS * OUT_F) + (size_t)b * OUT_F + o0;
            float4 v1 = *(float4*)&D[(size_t)r0 * DPITCH + colq * 4];
            float4 v2 = *(float4*)&D[REG2 + (size_t)r0 * DPITCH + colq * 4];
            float* p1 = &v1.x; float* p2 = &v2.x;
            #pragma unroll
            for (int j = 0; j < 4; j++) {
                float m = (o0 + j == lv) ? MARGIN : 0.0f;
                p1[j] = SC * (fminf(fmaxf(p1[j], -1.0f), 1.0f) - m);
                p2[j] = SC * (fminf(fmaxf(p2[j], -1.0f), 1.0f) - m);
            }
            *(float4*)(out + basep)        = v1;
            *(float4*)(out + OFF2 + basep) = v2;
        }
    }
}

// ---------------------------------------------------------------------------
extern "C" void kernel_launch(void* const* d_in, const int* in_sizes, int n_in,
                              void* d_out, int out_size) {
    const float* input  = (const float*)d_in[0];
    const int*   label  = (const int*)d_in[1];
    const float* weight = (const float*)d_in[2];
    const float* mlp    = (const float*)d_in[3];
    const float* cb     = (const float*)d_in[4];
    float*       out    = (float*)d_out;
    (void)in_sizes; (void)n_in; (void)out_size;

    cudaFuncSetAttribute(k_gemm_wm, cudaFuncAttributeMaxDynamicSharedMemorySize, DYN_SMEM);
    cudaFuncSetAttribute(k_feat, cudaFuncAttributeMaxDynamicSharedMemorySize, F_DYN);

    k_norm_w<<<BOOKS * OUT_F / 8, 256>>>(weight);
    k_split_mlp<<<BOOKS * LW * WORDS / 1024, 256>>>(mlp);
    k_transpose_cb<<<dim3(LW / 32, WORDS / 32, BOOKS), dim3(32, 8)>>>(cb);
    k_feat<<<dim3(N_ROWS / 64, BOOKS), 256, F_DYN>>>(input, out);
    k_gemm_wm<<<dim3(OUT_F / 128, N_ROWS / 128, BOOKS), 512, DYN_SMEM>>>(label, out);
}

// round 11
// speedup vs baseline: 1.4120x; 1.4120x over previous
#include <cuda_runtime.h>
#include <cuda_bf16.h>
#include <mma.h>
#include <math.h>
#include <stdint.h>

using namespace nvcuda;

// Problem constants
#define N_ROWS   1024
#define IN_F     2048
#define BOOKS    8
#define OUT_F    4096
#define LW       256
#define WORDS    256
#define SC       30.0f
#define MARGIN   0.5f
#define EPS      1e-12f

#define OUT1_ELEMS ((size_t)N_ROWS * BOOKS * OUT_F)
#define OFF2       OUT1_ELEMS
#define OFF3       (2 * OUT1_ELEMS)

// bf16 hi/lo split operands (emulated fp32 via 3 bf16 MMAs)
__device__ __nv_bfloat16 g_xh[BOOKS * N_ROWS * LW];
__device__ __nv_bfloat16 g_xl[BOOKS * N_ROWS * LW];
__device__ __nv_bfloat16 g_sh[BOOKS * N_ROWS * LW];
__device__ __nv_bfloat16 g_sl[BOOKS * N_ROWS * LW];
__device__ __nv_bfloat16 g_wh[BOOKS * OUT_F * LW];
__device__ __nv_bfloat16 g_wl[BOOKS * OUT_F * LW];
__device__ __nv_bfloat16 g_mh[BOOKS * LW * WORDS];
__device__ __nv_bfloat16 g_ml[BOOKS * LW * WORDS];
__device__ __nv_bfloat16 g_cbTh[BOOKS * WORDS * LW];
__device__ __nv_bfloat16 g_cbTl[BOOKS * WORDS * LW];

__device__ __forceinline__ uint32_t smem_u32(const void* p) {
    uint32_t a;
    asm("{ .reg .u64 t; cvta.to.shared.u64 t, %1; cvt.u32.u64 %0, t; }"
        : "=r"(a) : "l"(p));
    return a;
}

#define CP_ASYNC16(dst, src) \
    asm volatile("cp.async.cg.shared.global [%0], [%1], 16;" \
        :: "r"(dst), "l"(src) : "memory")
#define CP_COMMIT() asm volatile("cp.async.commit_group;" ::: "memory")
#define CP_WAIT(n)  asm volatile("cp.async.wait_group %0;" :: "n"(n) : "memory")

__device__ __forceinline__ void split_bf16(float v, __nv_bfloat16& h, __nv_bfloat16& l) {
    h = __float2bfloat16(v);
    l = __float2bfloat16(v - __bfloat162float(h));
}

// ---------------------------------------------------------------------------
// Kernel 1: row-normalize weight -> bf16 hi/lo. One warp per 256-elem row.
// ---------------------------------------------------------------------------
__global__ void __launch_bounds__(256) k_norm_w(const float* __restrict__ w) {
    int row  = blockIdx.x * 8 + (threadIdx.x >> 5);
    int lane = threadIdx.x & 31;
    const float* src = w + (size_t)row * LW + lane * 8;
    float4 a = *(const float4*)src;
    float4 c = *(const float4*)(src + 4);
    float ss = a.x*a.x + a.y*a.y + a.z*a.z + a.w*a.w
             + c.x*c.x + c.y*c.y + c.z*c.z + c.w*c.w;
    #pragma unroll
    for (int off = 16; off; off >>= 1) ss += __shfl_xor_sync(0xffffffffu, ss, off);
    float inv = 1.0f / fmaxf(sqrtf(ss), EPS);
    __align__(16) __nv_bfloat16 h8[8], l8[8];
    float v[8] = {a.x, a.y, a.z, a.w, c.x, c.y, c.z, c.w};
    #pragma unroll
    for (int j = 0; j < 8; j++) split_bf16(v[j] * inv, h8[j], l8[j]);
    *(uint4*)(g_wh + (size_t)row * LW + lane * 8) = *(uint4*)h8;
    *(uint4*)(g_wl + (size_t)row * LW + lane * 8) = *(uint4*)l8;
}

// ---------------------------------------------------------------------------
// Kernel 2a: elementwise split of mlp -> g_mh/g_ml
// ---------------------------------------------------------------------------
__global__ void __launch_bounds__(256) k_split_mlp(const float* __restrict__ m) {
    size_t i = ((size_t)blockIdx.x * 256 + threadIdx.x) * 4;
    float4 v = *(const float4*)(m + i);
    __align__(8) __nv_bfloat16 h4[4], l4[4];
    split_bf16(v.x, h4[0], l4[0]); split_bf16(v.y, h4[1], l4[1]);
    split_bf16(v.z, h4[2], l4[2]); split_bf16(v.w, h4[3], l4[3]);
    *(uint2*)(g_mh + i) = *(uint2*)h4;
    *(uint2*)(g_ml + i) = *(uint2*)l4;
}

// ---------------------------------------------------------------------------
// Kernel 2b: transpose codebooks + split: cbT[b][w][d] = cb[b][d][w]
// ---------------------------------------------------------------------------
__global__ void k_transpose_cb(const float* __restrict__ cb) {
    __shared__ float t[32][33];
    int b  = blockIdx.z;
    int d0 = blockIdx.x * 32;
    int w0 = blockIdx.y * 32;
    const float* src = cb + (size_t)b * LW * WORDS;
    for (int i = threadIdx.y; i < 32; i += 8)
        t[i][threadIdx.x] = src[(size_t)(d0 + i) * WORDS + w0 + threadIdx.x];
    __syncthreads();
    for (int i = threadIdx.y; i < 32; i += 8) {
        float v = t[threadIdx.x][i];
        __nv_bfloat16 h, l;
        split_bf16(v, h, l);
        size_t o = (size_t)b * WORDS * LW + (size_t)(w0 + i) * LW + d0 + threadIdx.x;
        g_cbTh[o] = h;
        g_cbTl[o] = l;
    }
}

// ---------------------------------------------------------------------------
// Kernel 3: WMMA bf16x3 features. One CTA per (book, 64 rows). 256 threads.
// (unchanged from R5)
// ---------------------------------------------------------------------------
#define FLDA 264
#define FLDL 260
#define F_XA_H 0
#define F_XA_L 33792
#define F_BB_H 67584
#define F_BB_L 101376
#define F_LL   135168
#define F_DYN  (F_LL + 64 * FLDL * 4)

__global__ void __launch_bounds__(256) k_feat(const float* __restrict__ input,
                                              float* __restrict__ out) {
    extern __shared__ __align__(16) char fsm[];
    __nv_bfloat16* XH = (__nv_bfloat16*)(fsm + F_XA_H);
    __nv_bfloat16* XL = (__nv_bfloat16*)(fsm + F_XA_L);
    __nv_bfloat16* BH = (__nv_bfloat16*)(fsm + F_BB_H);
    __nv_bfloat16* BL = (__nv_bfloat16*)(fsm + F_BB_L);
    float*         LL = (float*)(fsm + F_LL);
    __shared__ float part[64][4];
    __shared__ float rinv[64];

    int tid = threadIdx.x, wid = tid >> 5, lane = tid & 31;
    int n0 = blockIdx.x * 64;
    int b  = blockIdx.y;

    {
        int r = tid >> 2, q = tid & 3;
        const float* srcp = input + (size_t)(n0 + r) * IN_F + b * LW + q * 64;
        float ss = 0.0f;
        #pragma unroll
        for (int j = 0; j < 16; j++) {
            float4 v = *(const float4*)(srcp + j * 4);
            __align__(8) __nv_bfloat16 h4[4], l4[4];
            split_bf16(v.x, h4[0], l4[0]); split_bf16(v.y, h4[1], l4[1]);
            split_bf16(v.z, h4[2], l4[2]); split_bf16(v.w, h4[3], l4[3]);
            int c = q * 64 + j * 4;
            *(uint2*)&XH[r * FLDA + c] = *(uint2*)h4;
            *(uint2*)&XL[r * FLDA + c] = *(uint2*)l4;
            ss += v.x*v.x + v.y*v.y + v.z*v.z + v.w*v.w;
        }
        part[r][q] = ss;
    }
    __syncthreads();
    if (tid < 64)
        rinv[tid] = 1.0f / fmaxf(sqrtf(part[tid][0] + part[tid][1] +
                                       part[tid][2] + part[tid][3]), EPS);
    __syncthreads();

    {
        int r = tid >> 2, q = tid & 3;
        float iv = rinv[r];
        const float* srcp = input + (size_t)(n0 + r) * IN_F + b * LW + q * 64;
        size_t go = ((size_t)b * N_ROWS + n0 + r) * LW + q * 64;
        #pragma unroll
        for (int j = 0; j < 16; j++) {
            float4 v = *(const float4*)(srcp + j * 4);
            __align__(8) __nv_bfloat16 h4[4], l4[4];
            split_bf16(v.x * iv, h4[0], l4[0]); split_bf16(v.y * iv, h4[1], l4[1]);
            split_bf16(v.z * iv, h4[2], l4[2]); split_bf16(v.w * iv, h4[3], l4[3]);
            *(uint2*)(g_xh + go + j * 4) = *(uint2*)h4;
            *(uint2*)(g_xl + go + j * 4) = *(uint2*)l4;
        }
    }

    int wm = wid >> 2;
    int wn = wid & 3;
    wmma::fragment<wmma::accumulator, 16, 16, 16, float> acc[2][4];

    // ================= GEMM 1: logits = x @ mlp =================
    #pragma unroll
    for (int im = 0; im < 2; im++)
        #pragma unroll
        for (int jn = 0; jn < 4; jn++) wmma::fill_fragment(acc[im][jn], 0.0f);

    for (int kc = 0; kc < 4; kc++) {
        __syncthreads();
        const __nv_bfloat16* gbh = g_mh + (size_t)b * LW * WORDS + (size_t)kc * 64 * WORDS;
        const __nv_bfloat16* gbl = g_ml + (size_t)b * LW * WORDS + (size_t)kc * 64 * WORDS;
        #pragma unroll
        for (int j = 0; j < 8; j++) {
            int u = j * 256 + tid, row = u >> 5, seg = u & 31;
            *(uint4*)&BH[row * FLDA + seg * 8] = *(const uint4*)(gbh + row * 256 + seg * 8);
            *(uint4*)&BL[row * FLDA + seg * 8] = *(const uint4*)(gbl + row * 256 + seg * 8);
        }
        __syncthreads();
        #pragma unroll
        for (int k = 0; k < 4; k++) {
            wmma::fragment<wmma::matrix_a, 16, 16, 16, __nv_bfloat16, wmma::row_major> ah[2], al[2];
            #pragma unroll
            for (int im = 0; im < 2; im++) {
                int r0 = wm * 32 + im * 16;
                wmma::load_matrix_sync(ah[im], XH + r0 * FLDA + kc * 64 + k * 16, FLDA);
                wmma::load_matrix_sync(al[im], XL + r0 * FLDA + kc * 64 + k * 16, FLDA);
            }
            #pragma unroll
            for (int jn = 0; jn < 4; jn++) {
                int c0 = wn * 64 + jn * 16;
                wmma::fragment<wmma::matrix_b, 16, 16, 16, __nv_bfloat16, wmma::row_major> bh, bl;
                wmma::load_matrix_sync(bh, BH + (k * 16) * FLDA + c0, FLDA);
                wmma::load_matrix_sync(bl, BL + (k * 16) * FLDA + c0, FLDA);
                #pragma unroll
                for (int im = 0; im < 2; im++) {
                    wmma::mma_sync(acc[im][jn], ah[im], bh, acc[im][jn]);
                    wmma::mma_sync(acc[im][jn], ah[im], bl, acc[im][jn]);
                    wmma::mma_sync(acc[im][jn], al[im], bh, acc[im][jn]);
                }
            }
        }
    }
    __syncthreads();
    #pragma unroll
    for (int im = 0; im < 2; im++)
        #pragma unroll
        for (int jn = 0; jn < 4; jn++)
            wmma::store_matrix_sync(LL + (wm * 32 + im * 16) * FLDL + wn * 64 + jn * 16,
                                    acc[im][jn], FLDL, wmma::mem_row_major);
    __syncthreads();

    // ---- softmax per row
    #pragma unroll
    for (int rr = 0; rr < 8; rr++) {
        int r = wid * 8 + rr;
        float4 va = *(float4*)&LL[r * FLDL + lane * 8];
        float4 vb = *(float4*)&LL[r * FLDL + lane * 8 + 4];
        float v[8] = {va.x, va.y, va.z, va.w, vb.x, vb.y, vb.z, vb.w};
        float mx = v[0];
        #pragma unroll
        for (int j = 1; j < 8; j++) mx = fmaxf(mx, v[j]);
        #pragma unroll
        for (int off = 16; off; off >>= 1) mx = fmaxf(mx, __shfl_xor_sync(0xffffffffu, mx, off));
        float sm = 0.0f;
        #pragma unroll
        for (int j = 0; j < 8; j++) { v[j] = expf(v[j] - mx); sm += v[j]; }
        #pragma unroll
        for (int off = 16; off; off >>= 1) sm += __shfl_xor_sync(0xffffffffu, sm, off);
        float inv = 1.0f / sm;
        __align__(16) __nv_bfloat16 h8[8], l8[8];
        #pragma unroll
        for (int j = 0; j < 8; j++) { v[j] *= inv; split_bf16(v[j], h8[j], l8[j]); }
        float* po = out + OFF3 + (size_t)(n0 + r) * (BOOKS * WORDS) + b * WORDS + lane * 8;
        *(float4*)po       = make_float4(v[0], v[1], v[2], v[3]);
        *(float4*)(po + 4) = make_float4(v[4], v[5], v[6], v[7]);
        *(uint4*)&XH[r * FLDA + lane * 8] = *(uint4*)h8;
        *(uint4*)&XL[r * FLDA + lane * 8] = *(uint4*)l8;
    }
    __syncthreads();

    // ================= GEMM 2: s = xc @ cbT =================
    #pragma unroll
    for (int im = 0; im < 2; im++)
        #pragma unroll
        for (int jn = 0; jn < 4; jn++) wmma::fill_fragment(acc[im][jn], 0.0f);

    for (int kc = 0; kc < 4; kc++) {
        __syncthreads();
        const __nv_bfloat16* gbh = g_cbTh + (size_t)b * WORDS * LW + (size_t)kc * 64 * LW;
        const __nv_bfloat16* gbl = g_cbTl + (size_t)b * WORDS * LW + (size_t)kc * 64 * LW;
        #pragma unroll
        for (int j = 0; j < 8; j++) {
            int u = j * 256 + tid, row = u >> 5, seg = u & 31;
            *(uint4*)&BH[row * FLDA + seg * 8] = *(const uint4*)(gbh + row * 256 + seg * 8);
            *(uint4*)&BL[row * FLDA + seg * 8] = *(const uint4*)(gbl + row * 256 + seg * 8);
        }
        __syncthreads();
        #pragma unroll
        for (int k = 0; k < 4; k++) {
            wmma::fragment<wmma::matrix_a, 16, 16, 16, __nv_bfloat16, wmma::row_major> ah[2], al[2];
            #pragma unroll
            for (int im = 0; im < 2; im++) {
                int r0 = wm * 32 + im * 16;
                wmma::load_matrix_sync(ah[im], XH + r0 * FLDA + kc * 64 + k * 16, FLDA);
                wmma::load_matrix_sync(al[im], XL + r0 * FLDA + kc * 64 + k * 16, FLDA);
            }
            #pragma unroll
            for (int jn = 0; jn < 4; jn++) {
                int c0 = wn * 64 + jn * 16;
                wmma::fragment<wmma::matrix_b, 16, 16, 16, __nv_bfloat16, wmma::row_major> bh, bl;
                wmma::load_matrix_sync(bh, BH + (k * 16) * FLDA + c0, FLDA);
                wmma::load_matrix_sync(bl, BL + (k * 16) * FLDA + c0, FLDA);
                #pragma unroll
                for (int im = 0; im < 2; im++) {
                    wmma::mma_sync(acc[im][jn], ah[im], bh, acc[im][jn]);
                    wmma::mma_sync(acc[im][jn], ah[im], bl, acc[im][jn]);
                    wmma::mma_sync(acc[im][jn], al[im], bh, acc[im][jn]);
                }
            }
        }
    }
    __syncthreads();
    #pragma unroll
    for (int im = 0; im < 2; im++)
        #pragma unroll
        for (int jn = 0; jn < 4; jn++)
            wmma::store_matrix_sync(LL + (wm * 32 + im * 16) * FLDL + wn * 64 + jn * 16,
                                    acc[im][jn], FLDL, wmma::mem_row_major);
    __syncthreads();

    #pragma unroll
    for (int rr = 0; rr < 8; rr++) {
        int r = wid * 8 + rr;
        float4 va = *(float4*)&LL[r * FLDL + lane * 8];
        float4 vb = *(float4*)&LL[r * FLDL + lane * 8 + 4];
        float v[8] = {va.x, va.y, va.z, va.w, vb.x, vb.y, vb.z, vb.w};
        float ss = 0.0f;
        #pragma unroll
        for (int j = 0; j < 8; j++) ss += v[j] * v[j];
        #pragma unroll
        for (int off = 16; off; off >>= 1) ss += __shfl_xor_sync(0xffffffffu, ss, off);
        float inv = 1.0f / fmaxf(sqrtf(ss), EPS);
        __align__(16) __nv_bfloat16 h8[8], l8[8];
        #pragma unroll
        for (int j = 0; j < 8; j++) split_bf16(v[j] * inv, h8[j], l8[j]);
        size_t go = ((size_t)b * N_ROWS + n0 + r) * LW + lane * 8;
        *(uint4*)(g_sh + go) = *(uint4*)h8;
        *(uint4*)(g_sl + go) = *(uint4*)l8;
    }
}

// ---------------------------------------------------------------------------
// Kernel 4 v3: WMMA bf16x3 dual GEMM, 64x128 CTA tile, 2 CTAs/SM.
// 256 threads / 8 warps: wm = wid&1 (32-row blk), wn = wid>>1 (32-col blk).
// K = 256 in 8 chunks of 32, cp.async double-buffered, pitch 40 bf16 (80B,
// ldmatrix conflict-free: 80*i mod 128 distinct for i=0..7).
// ---------------------------------------------------------------------------
#define GP       40                    // smem pitch in bf16 elems
#define GPB      80                    // pitch bytes
#define GA_TB    (64 * GPB)            // 5120  A-tile bytes
#define GW_TB    (128 * GPB)           // 10240 W-tile bytes
#define G_XH     0
#define G_XL     5120
#define G_SH     10240
#define G_SL     15360
#define G_WH     20480
#define G_WL     30720
#define G_STAGE  40960
#define G_DYN    (2 * G_STAGE)         // 81920
#define G_DP     132                   // epilogue fp32 pitch
#define G_R2     (64 * G_DP)

__global__ void __launch_bounds__(256, 2) k_gemm3(const int* __restrict__ label,
                                                  float* __restrict__ out) {
    extern __shared__ __align__(16) char dsm[];
    __nv_bfloat16* smt = (__nv_bfloat16*)dsm;
    __shared__ int s_lbl[64];

    int tid = threadIdx.x;
    int wid = tid >> 5, lane = tid & 31;
    int nt = blockIdx.x, mt = blockIdx.y, b = blockIdx.z;
    uint32_t smbase = smem_u32(dsm);

    if (tid < 64) s_lbl[tid] = label[mt * 64 + tid];

    const char* pXH = (const char*)(g_xh + ((size_t)b * N_ROWS + mt * 64) * LW);
    const char* pXL = (const char*)(g_xl + ((size_t)b * N_ROWS + mt * 64) * LW);
    const char* pSH = (const char*)(g_sh + ((size_t)b * N_ROWS + mt * 64) * LW);
    const char* pSL = (const char*)(g_sl + ((size_t)b * N_ROWS + mt * 64) * LW);
    const char* pWH = (const char*)(g_wh + ((size_t)b * OUT_F  + nt * 128) * LW);
    const char* pWL = (const char*)(g_wl + ((size_t)b * OUT_F  + nt * 128) * LW);

    // A tile: 64 rows x 4 16B-segs = 256 -> 1 per thread.
    // W tile: 128 rows x 4 segs = 512 -> 2 per thread.
#define LDA3(ptr, off, c_, st_) { \
    int row = tid >> 2, seg = tid & 3; \
    CP_ASYNC16(smbase + (st_) * G_STAGE + (off) + row * GPB + seg * 16, \
               (ptr) + (size_t)row * 512 + (c_) * 64 + seg * 16); }
#define LDW3(ptr, off, c_, st_) { \
    _Pragma("unroll") for (int j = 0; j < 2; j++) { \
        int u = j * 256 + tid; int row = u >> 2, seg = u & 3; \
        CP_ASYNC16(smbase + (st_) * G_STAGE + (off) + row * GPB + seg * 16, \
                   (ptr) + (size_t)row * 512 + (c_) * 64 + seg * 16); } }
#define LOAD_CHUNK3(c_, st_) { \
    LDA3(pXH, G_XH, c_, st_); LDA3(pXL, G_XL, c_, st_); \
    LDA3(pSH, G_SH, c_, st_); LDA3(pSL, G_SL, c_, st_); \
    LDW3(pWH, G_WH, c_, st_); LDW3(pWL, G_WL, c_, st_); \
    CP_COMMIT(); }

    int wm = wid & 1;        // 0..1 : 32-row block
    int wn = wid >> 1;       // 0..3 : 32-col block

    wmma::fragment<wmma::accumulator, 16, 16, 16, float> acc1[2][2], acc2[2][2];
    #pragma unroll
    for (int im = 0; im < 2; im++)
        #pragma unroll
        for (int jn = 0; jn < 2; jn++) {
            wmma::fill_fragment(acc1[im][jn], 0.0f);
            wmma::fill_fragment(acc2[im][jn], 0.0f);
        }

    LOAD_CHUNK3(0, 0);
    LOAD_CHUNK3(1, 1);

    #pragma unroll 1
    for (int c = 0; c < 8; c++) {
        if (c < 7) { CP_WAIT(1); } else { CP_WAIT(0); }
        __syncthreads();
        {
            int st = c & 1;
            const __nv_bfloat16* base = smt + st * (G_STAGE / 2);
            const __nv_bfloat16* tXH = base + G_XH / 2;
            const __nv_bfloat16* tXL = base + G_XL / 2;
            const __nv_bfloat16* tSH = base + G_SH / 2;
            const __nv_bfloat16* tSL = base + G_SL / 2;
            const __nv_bfloat16* tWH = base + G_WH / 2;
            const __nv_bfloat16* tWL = base + G_WL / 2;
            #pragma unroll
            for (int k = 0; k < 2; k++) {
                wmma::fragment<wmma::matrix_b, 16, 16, 16, __nv_bfloat16, wmma::col_major> bwh[2], bwl[2];
                #pragma unroll
                for (int jn = 0; jn < 2; jn++) {
                    int c0 = wn * 32 + jn * 16;
                    wmma::load_matrix_sync(bwh[jn], tWH + c0 * GP + k * 16, GP);
                    wmma::load_matrix_sync(bwl[jn], tWL + c0 * GP + k * 16, GP);
                }
                #pragma unroll
                for (int im = 0; im < 2; im++) {
                    int r0 = wm * 32 + im * 16;
                    wmma::fragment<wmma::matrix_a, 16, 16, 16, __nv_bfloat16, wmma::row_major> axh, axl, ash, asl;
                    wmma::load_matrix_sync(axh, tXH + r0 * GP + k * 16, GP);
                    wmma::load_matrix_sync(axl, tXL + r0 * GP + k * 16, GP);
                    wmma::load_matrix_sync(ash, tSH + r0 * GP + k * 16, GP);
                    wmma::load_matrix_sync(asl, tSL + r0 * GP + k * 16, GP);
                    #pragma unroll
                    for (int jn = 0; jn < 2; jn++) {
                        wmma::mma_sync(acc1[im][jn], axh, bwh[jn], acc1[im][jn]);
                        wmma::mma_sync(acc1[im][jn], axh, bwl[jn], acc1[im][jn]);
                        wmma::mma_sync(acc1[im][jn], axl, bwh[jn], acc1[im][jn]);
                        wmma::mma_sync(acc2[im][jn], ash, bwh[jn], acc2[im][jn]);
                        wmma::mma_sync(acc2[im][jn], ash, bwl[jn], acc2[im][jn]);
                        wmma::mma_sync(acc2[im][jn], asl, bwh[jn], acc2[im][jn]);
                    }
                }
            }
        }
        __syncthreads();
        if (c + 2 < 8) { LOAD_CHUNK3(c + 2, c & 1); }
    }

    // Epilogue: stage D (64x128 x2) in smem, then coalesced clip/margin/scale.
    float* D = (float*)dsm;
    #pragma unroll
    for (int im = 0; im < 2; im++)
        #pragma unroll
        for (int jn = 0; jn < 2; jn++) {
            int r0 = wm * 32 + im * 16;
            int c0 = wn * 32 + jn * 16;
            wmma::store_matrix_sync(D + (size_t)r0 * G_DP + c0, acc1[im][jn],
                                    G_DP, wmma::mem_row_major);
            wmma::store_matrix_sync(D + G_R2 + (size_t)r0 * G_DP + c0, acc2[im][jn],
                                    G_DP, wmma::mem_row_major);
        }
    __syncthreads();

    {
        for (int r0 = wid; r0 < 64; r0 += 8) {
            int lv = s_lbl[r0];
            int o0 = nt * 128 + lane * 4;
            size_t basep = (size_t)(mt * 64 + r0) * (BOOKS * OUT_F) + (size_t)b * OUT_F + o0;
            float4 v1 = *(float4*)&D[(size_t)r0 * G_DP + lane * 4];
            float4 v2 = *(float4*)&D[G_R2 + (size_t)r0 * G_DP + lane * 4];
            float* p1 = &v1.x; float* p2 = &v2.x;
            #pragma unroll
            for (int j = 0; j < 4; j++) {
                float m = (o0 + j == lv) ? MARGIN : 0.0f;
                p1[j] = SC * (fminf(fmaxf(p1[j], -1.0f), 1.0f) - m);
                p2[j] = SC * (fminf(fmaxf(p2[j], -1.0f), 1.0f) - m);
            }
            *(float4*)(out + basep)        = v1;
            *(float4*)(out + OFF2 + basep) = v2;
        }
    }
}

// ---------------------------------------------------------------------------
extern "C" void kernel_launch(void* const* d_in, const int* in_sizes, int n_in,
                              void* d_out, int out_size) {
    const float* input  = (const float*)d_in[0];
    const int*   label  = (const int*)d_in[1];
    const float* weight = (const float*)d_in[2];
    const float* mlp    = (const float*)d_in[3];
    const float* cb     = (const float*)d_in[4];
    float*       out    = (float*)d_out;
    (void)in_sizes; (void)n_in; (void)out_size;

    cudaFuncSetAttribute(k_gemm3, cudaFuncAttributeMaxDynamicSharedMemorySize, G_DYN);
    cudaFuncSetAttribute(k_feat, cudaFuncAttributeMaxDynamicSharedMemorySize, F_DYN);

    k_norm_w<<<BOOKS * OUT_F / 8, 256>>>(weight);
    k_split_mlp<<<BOOKS * LW * WORDS / 1024, 256>>>(mlp);
    k_transpose_cb<<<dim3(LW / 32, WORDS / 32, BOOKS), dim3(32, 8)>>>(cb);
    k_feat<<<dim3(N_ROWS / 64, BOOKS), 256, F_DYN>>>(input, out);
    k_gemm3<<<dim3(OUT_F / 128, N_ROWS / 64, BOOKS), 256, G_DYN>>>(label, out);
}